// round 2
// baseline (speedup 1.0000x reference)
#include <cuda_runtime.h>
#include <math.h>

#define N 8192
#define D 1024

// Scratch (allocation-free rule: __device__ globals)
__device__ float g_a[N];        // sigmoid(x @ w)
__device__ float g_b[N];        // cumsum(a), replicating jax associative_scan fp32 tree
__device__ float g_m[N];        // main weight (written at row idx in reference)
__device__ float g_c[N];        // cross weight (written at row idx-1), 0 if same bin
__device__ int   g_idx[N];      // floor(b) per column
__device__ int   g_start[N];    // first column relevant to output row j
__device__ int   g_end[N];      // one past last column relevant to output row j

// ---------------------------------------------------------------------------
// Kernel 1: z = x @ w, a = sigmoid(z).  Two rows per warp (doubles MLP).
// NOTE: per-row accumulation order is kept IDENTICAL to the validated R1
// kernel (same FFMA chain, same shfl tree) so g_a is bitwise unchanged.
// ---------------------------------------------------------------------------
__global__ void k_logits(const float* __restrict__ x, const float* __restrict__ w) {
    const int warp = threadIdx.x >> 5;
    const int lane = threadIdx.x & 31;
    const int row  = (blockIdx.x * 8 + warp) * 2;   // 8 warps/block, 2 rows/warp

    const float4* w4  = reinterpret_cast<const float4*>(w);
    const float4* xr0 = reinterpret_cast<const float4*>(x) + (size_t)row * (D / 4);
    const float4* xr1 = xr0 + (D / 4);

    float s0 = 0.f, s1 = 0.f;
#pragma unroll
    for (int k = 0; k < D / 128; k++) {             // 8 iterations
        float4 wv = __ldg(&w4[lane + 32 * k]);
        float4 v0 = xr0[lane + 32 * k];
        float4 v1 = xr1[lane + 32 * k];
        s0 += v0.x * wv.x;
        s0 += v0.y * wv.y;
        s0 += v0.z * wv.z;
        s0 += v0.w * wv.w;
        s1 += v1.x * wv.x;
        s1 += v1.y * wv.y;
        s1 += v1.z * wv.z;
        s1 += v1.w * wv.w;
    }
#pragma unroll
    for (int off = 16; off; off >>= 1) {
        s0 += __shfl_xor_sync(0xffffffffu, s0, off);
        s1 += __shfl_xor_sync(0xffffffffu, s1, off);
    }

    if (lane == 0) {
#pragma unroll
        for (int r = 0; r < 2; r++) {
            float z = (r == 0) ? s0 : s1, a;
            if (z >= 0.f) {
                a = 1.f / (1.f + expf(-z));
            } else {
                float e = expf(z);
                a = e / (1.f + e);
            }
            g_a[row + r] = a;
        }
    }
}

// ---------------------------------------------------------------------------
// Kernel 2: b = cumsum(a) replicating jax.lax.associative_scan's fp32 tree,
// then derive per-column weights AND exact per-output-row column spans.
// ---------------------------------------------------------------------------
__global__ void k_scan() {
    __shared__ float sh[8192];
    const int tid = threadIdx.x;   // 1024 threads

    // init span arrays (reset every replay; atomics below refine them)
    for (int i = tid; i < N; i += 1024) {
        g_start[i] = N;
        g_end[i]   = 0;
    }

    // up-sweep: level 1 from global a
    for (int i = tid; i < 4096; i += 1024)
        sh[i] = g_a[2 * i] + g_a[2 * i + 1];
    __syncthreads();
    for (int l = 2; l <= 13; l++) {
        const int n    = N >> l;
        const int off  = 8192 - 2 * (8192 >> l);
        const int offp = 8192 - 2 * (8192 >> (l - 1));
        for (int i = tid; i < n; i += 1024)
            sh[off + i] = sh[offp + 2 * i] + sh[offp + 2 * i + 1];
        __syncthreads();
    }

    // down-sweep (in place per level)
    for (int l = 12; l >= 1; l--) {
        const int n    = N >> l;
        const int off  = 8192 - 2 * (8192 >> l);
        const int offc = 8192 - 2 * (8192 >> (l + 1));
        for (int i = tid; i < n; i += 1024) {
            float v;
            if (i & 1)       v = sh[offc + (i >> 1)];
            else if (i == 0) v = sh[off];
            else             v = sh[offc + (i >> 1) - 1] + sh[off + i];
            sh[off + i] = v;
        }
        __syncthreads();
    }

    // level 0 -> g_b
    for (int i = tid; i < N; i += 1024) {
        float v;
        if (i == 0)      v = g_a[0];
        else if (i & 1)  v = sh[i >> 1];
        else             v = sh[(i >> 1) - 1] + g_a[i];
        g_b[i] = v;
    }
    __syncthreads();

    // derive idx / main / cross + register each column with the rows it
    // touches. Faithful to the reference for ANY idx pattern (no
    // monotonicity assumption).
    for (int i = tid; i < N; i += 1024) {
        const float b = g_b[i];
        const float a = g_a[i];
        int idx  = (int)floorf(b);
        int prev = (i == 0) ? 0 : (int)floorf(g_b[i - 1]);
        const bool same = (idx == prev);
        const float frac = b - (float)idx;

        g_m[i]   = same ? a : frac;
        g_c[i]   = same ? 0.f : (a - frac);
        g_idx[i] = idx;

        int i0 = idx;                        // main target row
        if (i0 >= 0 && i0 < N) {
            atomicMin(&g_start[i0], i);
            atomicMax(&g_end[i0], i + 1);
        }
        if (!same) {
            int i1 = idx - 1;                // cross target row
            if (i1 >= 0 && i1 < N) {
                atomicMin(&g_start[i1], i);
                atomicMax(&g_end[i1], i + 1);
            }
        }
    }
}

// ---------------------------------------------------------------------------
// Kernel 3: gather.  One block per output row j. Each column i in the exact
// span [start[j], end[j]) contributes m_i (if idx_i==j) or c_i (if
// idx_i==j+1). Rows with empty spans write zeros (d_out is poisoned).
// ---------------------------------------------------------------------------
__global__ void k_gather(const float* __restrict__ x, float* __restrict__ out) {
    const int j = blockIdx.x;     // output row
    const int t = threadIdx.x;    // 0..255, float4 lanes

    const int s = g_start[j];
    const int e = g_end[j];

    float4 acc = make_float4(0.f, 0.f, 0.f, 0.f);
    for (int i = s; i < e; i++) {
        const int idx = __ldg(&g_idx[i]);
        float wgt = 0.f;
        if (idx == j)          wgt = __ldg(&g_m[i]);
        else if (idx == j + 1) wgt = __ldg(&g_c[i]);
        if (wgt != 0.f) {       // warp-uniform; exact (zero weight = zero add)
            const float4 v = reinterpret_cast<const float4*>(x)[(size_t)i * (D / 4) + t];
            acc.x += wgt * v.x;
            acc.y += wgt * v.y;
            acc.z += wgt * v.z;
            acc.w += wgt * v.w;
        }
    }
    reinterpret_cast<float4*>(out)[(size_t)j * (D / 4) + t] = acc;
}

// ---------------------------------------------------------------------------
extern "C" void kernel_launch(void* const* d_in, const int* in_sizes, int n_in,
                              void* d_out, int out_size) {
    const float* x = (const float*)d_in[0];   // [8192, 1024] f32
    const float* w = (const float*)d_in[1];   // [1024, 1]    f32
    float* out = (float*)d_out;               // [8192, 1024] f32

    k_logits<<<N / 16, 256>>>(x, w);
    k_scan<<<1, 1024>>>();
    k_gather<<<N, 256>>>(x, out);
}